// round 10
// baseline (speedup 1.0000x reference)
#include <cuda_runtime.h>
#include <cuda_fp16.h>
#include <math.h>

// Problem constants (fixed by the dataset)
#define Cn   128
#define Hh   5
#define HC   (Hh*Cn)      // 640
#define MAXN 20000
#define MAXE 320000
#define MAXET (MAXE + MAXN)
#define EPSV 1e-16f
#define NEG_SLOPE 0.2f

// ---------------- scratch (static device globals) -----------------------------
__device__ __align__(16) __half g_h[(size_t)MAXN * HC];  // [N,H,C] fp16 (25.6 MB)
__device__ float g_asrc[MAXN * Hh];
__device__ float g_adst[MAXN * Hh];
__device__ float g_denom[MAXN * Hh];
__device__ int   g_cnt[MAXN];             // out-degree histogram / fill cursors
__device__ int2  g_sd[MAXET];             // src-grouped (src,dst) pairs

// ---------------- kernel 0: init out = features + bias; zero counters --------
__global__ void init_kernel(const float* __restrict__ features,
                            const float* __restrict__ bias,
                            float* __restrict__ out, int Nn) {
    int i = blockIdx.x * blockDim.x + threadIdx.x;
    int NC = Nn * Cn;
    if (i < NC) out[i] = features[i] + bias[i & (Cn - 1)];
    if (i < Nn * Hh) g_denom[i] = 0.0f;
    if (i < Nn) g_cnt[i] = 0;
}

// ---------------- kernel 1: out-degree histogram ------------------------------
__global__ void hist_kernel(const int* __restrict__ ei, int E, int Etot) {
    int e = blockIdx.x * blockDim.x + threadIdx.x;
    if (e >= Etot) return;
    int src = (e < E) ? ei[e] : (e - E);
    atomicAdd(&g_cnt[src], 1);
}

// ---------------- kernel 2: single-block exclusive scan; cnt -> cursors -------
__global__ __launch_bounds__(1024) void scan_kernel(int Nn) {
    __shared__ int s[1024];
    const int tid = threadIdx.x;
    const int CH  = (Nn + 1023) / 1024;     // 20
    int base = tid * CH;
    int loc[20];
    int sum = 0;
    for (int j = 0; j < CH; j++) {
        int idx = base + j;
        int v = (idx < Nn) ? g_cnt[idx] : 0;
        loc[j] = sum;
        sum += v;
    }
    s[tid] = sum;
    __syncthreads();
    int own = sum;
    for (int o = 1; o < 1024; o <<= 1) {
        int t = (tid >= o) ? s[tid - o] : 0;
        __syncthreads();
        s[tid] += t;
        __syncthreads();
    }
    int pre = s[tid] - own;
    for (int j = 0; j < CH; j++) {
        int idx = base + j;
        if (idx < Nn) g_cnt[idx] = pre + loc[j];   // reuse g_cnt as fill cursor
    }
}

// ---------------- kernel 3: CSR fill (src-grouped (src,dst) pairs) ------------
__global__ void fill_kernel(const int* __restrict__ ei, int E, int Etot) {
    int e = blockIdx.x * blockDim.x + threadIdx.x;
    if (e >= Etot) return;
    int src, dst;
    if (e < E) { src = ei[e]; dst = ei[E + e]; }
    else       { src = e - E; dst = src; }
    int pos = atomicAdd(&g_cnt[src], 1);
    g_sd[pos] = make_int2(src, dst);
}

// ---------------- tf32 TC GEMM, cp.async 2-stage pipeline + fused logits -----
#define TBM  128
#define TBK  32
#define APAD 36
#define BPAD 132
#define CH2S 69
#define AS_BYTES (TBM * APAD * 4)               // 18432
#define BS_BYTES (TBK * BPAD * 4)               // 16896
#define SMEM_DYN (2 * AS_BYTES + 2 * BS_BYTES)  // 70656

__device__ __forceinline__ void cp16(unsigned dst, const void* src) {
    asm volatile("cp.async.cg.shared.global [%0], [%1], 16;"
                 :: "r"(dst), "l"(src));
}

__device__ __forceinline__ void mma_tf32(float d[4], const unsigned a[4],
                                         const unsigned b[2]) {
    asm volatile(
        "mma.sync.aligned.m16n8k8.row.col.f32.tf32.tf32.f32 "
        "{%0,%1,%2,%3}, {%4,%5,%6,%7}, {%8,%9}, {%0,%1,%2,%3};"
        : "+f"(d[0]), "+f"(d[1]), "+f"(d[2]), "+f"(d[3])
        : "r"(a[0]), "r"(a[1]), "r"(a[2]), "r"(a[3]), "r"(b[0]), "r"(b[1]));
}

__global__ __launch_bounds__(256, 2)
void gemm_tc_kernel(const float* __restrict__ A,
                    const float* __restrict__ B,
                    const float* __restrict__ att_src,
                    const float* __restrict__ att_dst,
                    int M) {
    extern __shared__ __align__(16) char smem_raw[];
    unsigned* Cs = (unsigned*)smem_raw;

    const int tid    = threadIdx.x;
    const int head   = blockIdx.x;
    const int rowBlk = blockIdx.y * TBM;
    const int lane   = tid & 31;
    const int wid    = tid >> 5;
    const int warpM  = wid & 1;
    const int warpN  = wid >> 1;
    const int gid    = lane >> 2;
    const int tig    = lane & 3;

    float acc[4][4][4];
    #pragma unroll
    for (int m = 0; m < 4; m++)
        #pragma unroll
        for (int n = 0; n < 4; n++)
            #pragma unroll
            for (int r = 0; r < 4; r++) acc[m][n][r] = 0.0f;

    const int aRow   = tid >> 1;
    const int aCbase = (tid & 1) * 16;
    const int bKrow  = tid >> 3;
    const int bF4    = tid & 7;
    const int gARow  = rowBlk + aRow;
    const int safeAR = (gARow < M) ? gARow : 0;

    const unsigned sbase = (unsigned)__cvta_generic_to_shared(smem_raw);
    const float* apRow = A + (size_t)safeAR * Cn + aCbase;
    const float* bpRow = B + (size_t)bKrow * HC + head * Cn;

    {
        unsigned aB = sbase;
        unsigned bB = sbase + 2 * AS_BYTES;
        #pragma unroll
        for (int j = 0; j < 4; j++)
            cp16(aB + (aRow * APAD + aCbase + 4 * j) * 4, apRow + 4 * j);
        #pragma unroll
        for (int j = 0; j < 4; j++) {
            int col = (bF4 + 8 * j) * 4;
            cp16(bB + (bKrow * BPAD + col) * 4, bpRow + col);
        }
        asm volatile("cp.async.commit_group;");
    }

    #pragma unroll
    for (int c = 0; c < 4; c++) {
        if (c < 3) {
            int st = (c + 1) & 1;
            int kc = (c + 1) * TBK;
            unsigned aB = sbase + st * AS_BYTES;
            unsigned bB = sbase + 2 * AS_BYTES + st * BS_BYTES;
            #pragma unroll
            for (int j = 0; j < 4; j++)
                cp16(aB + (aRow * APAD + aCbase + 4 * j) * 4, apRow + kc + 4 * j);
            #pragma unroll
            for (int j = 0; j < 4; j++) {
                int col = (bF4 + 8 * j) * 4;
                cp16(bB + (bKrow * BPAD + col) * 4, bpRow + (size_t)kc * HC + col);
            }
            asm volatile("cp.async.commit_group;");
            asm volatile("cp.async.wait_group 1;");
        } else {
            asm volatile("cp.async.wait_group 0;");
        }
        __syncthreads();

        const float* Asp = (const float*)(smem_raw + (c & 1) * AS_BYTES);
        const float* Bsp = (const float*)(smem_raw + 2 * AS_BYTES + (c & 1) * BS_BYTES);

        #pragma unroll
        for (int kk = 0; kk < 4; kk++) {
            const int kb = kk * 8;
            unsigned a[4][4], b[4][2];
            #pragma unroll
            for (int m = 0; m < 4; m++) {
                int r0 = warpM * 64 + m * 16 + gid;
                a[m][0] = __float_as_uint(Asp[r0 * APAD + kb + tig]);
                a[m][1] = __float_as_uint(Asp[(r0 + 8) * APAD + kb + tig]);
                a[m][2] = __float_as_uint(Asp[r0 * APAD + kb + tig + 4]);
                a[m][3] = __float_as_uint(Asp[(r0 + 8) * APAD + kb + tig + 4]);
            }
            #pragma unroll
            for (int n = 0; n < 4; n++) {
                int cb = warpN * 32 + n * 8 + gid;
                b[n][0] = __float_as_uint(Bsp[(kb + tig) * BPAD + cb]);
                b[n][1] = __float_as_uint(Bsp[(kb + tig + 4) * BPAD + cb]);
            }
            #pragma unroll
            for (int m = 0; m < 4; m++)
                #pragma unroll
                for (int n = 0; n < 4; n++)
                    mma_tf32(acc[m][n], a[m], b[n]);
        }
        __syncthreads();
    }

    #pragma unroll
    for (int m = 0; m < 4; m++) {
        int r0 = warpM * 64 + m * 16 + gid;
        #pragma unroll
        for (int n = 0; n < 4; n++) {
            int ch = warpN * 16 + n * 4 + tig;
            __half2 h01 = __floats2half2_rn(acc[m][n][0], acc[m][n][1]);
            __half2 h23 = __floats2half2_rn(acc[m][n][2], acc[m][n][3]);
            Cs[r0 * CH2S + ch]       = *(unsigned*)&h01;
            Cs[(r0 + 8) * CH2S + ch] = *(unsigned*)&h23;
        }
    }
    __syncthreads();

    if (tid < TBM) {
        int gRow = rowBlk + tid;
        if (gRow < M) {
            const float* asv = att_src + head * Cn;
            const float* adv = att_dst + head * Cn;
            float ps = 0.f, pd = 0.f;
            #pragma unroll 8
            for (int i = 0; i < 64; i++) {
                unsigned u = Cs[tid * CH2S + i];
                float2 f = __half22float2(*(__half2*)&u);
                ps = fmaf(f.x, __ldg(asv + 2 * i), ps);
                ps = fmaf(f.y, __ldg(asv + 2 * i + 1), ps);
                pd = fmaf(f.x, __ldg(adv + 2 * i), pd);
                pd = fmaf(f.y, __ldg(adv + 2 * i + 1), pd);
            }
            g_asrc[gRow * Hh + head] = ps;
            g_adst[gRow * Hh + head] = pd;
        }
    }

    unsigned* gh = (unsigned*)g_h;
    #pragma unroll
    for (int i = 0; i < 32; i++) {
        int idx  = i * 256 + tid;
        int row  = idx >> 6;
        int ch   = idx & 63;
        int gRow = rowBlk + row;
        if (gRow < M)
            gh[(size_t)gRow * (HC / 2) + head * 64 + ch] = Cs[row * CH2S + ch];
    }
}

// ---------------- kernel 4: softmax denominators over CSR order --------------
__global__ void denom_kernel(int Etot) {
    int e = blockIdx.x * blockDim.x + threadIdx.x;
    if (e >= Etot) return;
    int2 sd = g_sd[e];
    #pragma unroll
    for (int h = 0; h < Hh; h++) {
        float v = g_asrc[sd.x * Hh + h] + g_adst[sd.y * Hh + h];
        v = v > 0.f ? v : NEG_SLOPE * v;
        atomicAdd(&g_denom[sd.y * Hh + h], __expf(v));
    }
}

// ---------------- helper: accumulate 4 fp16 channels of one head -------------
__device__ __forceinline__ void acc_head(float4& acc4, uint2 u, float wgt) {
    float2 lo = __half22float2(*(const __half2*)&u.x);
    float2 hi = __half22float2(*(const __half2*)&u.y);
    acc4.x = fmaf(wgt, lo.x, acc4.x);
    acc4.y = fmaf(wgt, lo.y, acc4.y);
    acc4.z = fmaf(wgt, hi.x, acc4.z);
    acc4.w = fmaf(wgt, hi.y, acc4.w);
}

// ---------------- kernel 5: scatter over CSR order (src-locality) ------------
__global__ __launch_bounds__(256)
void scatter_kernel(float* __restrict__ out, int Etot) {
    int e = blockIdx.x * (blockDim.x >> 5) + (threadIdx.x >> 5);
    if (e >= Etot) return;
    int lane = threadIdx.x & 31;

    int2 sd = g_sd[e];           // consecutive e -> same src: L1-resident h row
    int src = sd.x, dst = sd.y;

    float wv = 0.f;
    if (lane < Hh) {
        float v = g_asrc[src * Hh + lane] + g_adst[dst * Hh + lane];
        v = v > 0.f ? v : NEG_SLOPE * v;
        wv = __expf(v) / (g_denom[dst * Hh + lane] + EPSV) * (1.0f / Hh);
    }
    float w0 = __shfl_sync(0xffffffffu, wv, 0);
    float w1 = __shfl_sync(0xffffffffu, wv, 1);
    float w2 = __shfl_sync(0xffffffffu, wv, 2);
    float w3 = __shfl_sync(0xffffffffu, wv, 3);
    float w4 = __shfl_sync(0xffffffffu, wv, 4);

    const uint2* hp = (const uint2*)(g_h + (size_t)src * HC) + lane;
    uint2 u0 = hp[0 * 32];
    uint2 u1 = hp[1 * 32];
    uint2 u2 = hp[2 * 32];
    uint2 u3 = hp[3 * 32];
    uint2 u4 = hp[4 * 32];

    float4 a = make_float4(0.f, 0.f, 0.f, 0.f);
    acc_head(a, u0, w0);
    acc_head(a, u1, w1);
    acc_head(a, u2, w2);
    acc_head(a, u3, w3);
    acc_head(a, u4, w4);

    float* op = out + (size_t)dst * Cn + lane * 4;
    asm volatile("red.global.add.v4.f32 [%0], {%1, %2, %3, %4};"
                 :: "l"(op), "f"(a.x), "f"(a.y), "f"(a.z), "f"(a.w)
                 : "memory");
}

// ---------------- launch -------------------------------------------------------
extern "C" void kernel_launch(void* const* d_in, const int* in_sizes, int n_in,
                              void* d_out, int out_size) {
    const float* features = (const float*)d_in[0];
    const float* W        = (const float*)d_in[1];
    const float* att_src  = (const float*)d_in[2];
    const float* att_dst  = (const float*)d_in[3];
    const float* bias     = (const float*)d_in[4];
    const int*   ei       = (const int*)d_in[5];
    float*       out      = (float*)d_out;

    const int Nn   = in_sizes[0] / Cn;   // 20000
    const int E    = in_sizes[5] / 2;    // 320000
    const int Etot = E + Nn;             // 340000

    // 0) out = features + bias; zero denom + counters
    init_kernel<<<(Nn * Cn + 255) / 256, 256>>>(features, bias, out, Nn);

    // 1) CSR ordering: histogram -> scan -> fill (src-grouped (src,dst) pairs)
    hist_kernel<<<(Etot + 255) / 256, 256>>>(ei, E, Etot);
    scan_kernel<<<1, 1024>>>(Nn);
    fill_kernel<<<(Etot + 255) / 256, 256>>>(ei, E, Etot);

    // 2) h = features @ W via pipelined tf32 TC GEMM, fused logits
    {
        cudaFuncSetAttribute(gemm_tc_kernel,
                             cudaFuncAttributeMaxDynamicSharedMemorySize, SMEM_DYN);
        dim3 grid(Hh, (Nn + TBM - 1) / TBM);
        gemm_tc_kernel<<<grid, 256, SMEM_DYN>>>(features, W, att_src, att_dst, Nn);
    }

    // 3) softmax denominators (CSR order)
    denom_kernel<<<(Etot + 255) / 256, 256>>>(Etot);

    // 4) scatter (CSR order: src-locality for h reads)
    scatter_kernel<<<(Etot + 7) / 8, 256>>>(out, Etot);
}

// round 11
// speedup vs baseline: 1.2085x; 1.2085x over previous
#include <cuda_runtime.h>
#include <cuda_fp16.h>
#include <math.h>

// Problem constants (fixed by the dataset)
#define Cn   128
#define Hh   5
#define HC   (Hh*Cn)      // 640
#define MAXN 20000
#define MAXE 320000
#define MAXET (MAXE + MAXN)
#define EPSV 1e-16f
#define NEG_SLOPE 0.2f

// ---------------- scratch (static device globals) -----------------------------
__device__ __align__(16) __half g_h[(size_t)MAXN * HC];  // [N,H,C] fp16 (25.6 MB)
__device__ float g_asrc[MAXN * Hh];
__device__ float g_adst[MAXN * Hh];
__device__ float g_denom[MAXN * Hh];

// ---------------- tf32 TC GEMM, cp.async pipeline + fused logits + out-init --
#define TBM  128
#define TBK  32
#define APAD 36
#define BPAD 132
#define CH2S 69
#define AS_BYTES (TBM * APAD * 4)               // 18432
#define BS_BYTES (TBK * BPAD * 4)               // 16896
#define SMEM_DYN (2 * AS_BYTES + 2 * BS_BYTES)  // 70656

__device__ __forceinline__ void cp16(unsigned dst, const void* src) {
    asm volatile("cp.async.cg.shared.global [%0], [%1], 16;"
                 :: "r"(dst), "l"(src));
}

__device__ __forceinline__ void mma_tf32(float d[4], const unsigned a[4],
                                         const unsigned b[2]) {
    asm volatile(
        "mma.sync.aligned.m16n8k8.row.col.f32.tf32.tf32.f32 "
        "{%0,%1,%2,%3}, {%4,%5,%6,%7}, {%8,%9}, {%0,%1,%2,%3};"
        : "+f"(d[0]), "+f"(d[1]), "+f"(d[2]), "+f"(d[3])
        : "r"(a[0]), "r"(a[1]), "r"(a[2]), "r"(a[3]), "r"(b[0]), "r"(b[1]));
}

__global__ __launch_bounds__(256, 2)
void gemm_tc_kernel(const float* __restrict__ A,
                    const float* __restrict__ B,
                    const float* __restrict__ att_src,
                    const float* __restrict__ att_dst,
                    const float* __restrict__ bias,
                    float* __restrict__ out,
                    int M) {
    extern __shared__ __align__(16) char smem_raw[];
    unsigned* Cs = (unsigned*)smem_raw;

    const int tid    = threadIdx.x;
    const int head   = blockIdx.x;
    const int rowBlk = blockIdx.y * TBM;
    const int lane   = tid & 31;
    const int wid    = tid >> 5;
    const int warpM  = wid & 1;
    const int warpN  = wid >> 1;
    const int gid    = lane >> 2;
    const int tig    = lane & 3;

    float acc[4][4][4];
    #pragma unroll
    for (int m = 0; m < 4; m++)
        #pragma unroll
        for (int n = 0; n < 4; n++)
            #pragma unroll
            for (int r = 0; r < 4; r++) acc[m][n][r] = 0.0f;

    const int aRow   = tid >> 1;
    const int aCbase = (tid & 1) * 16;
    const int bKrow  = tid >> 3;
    const int bF4    = tid & 7;
    const int gARow  = rowBlk + aRow;
    const int safeAR = (gARow < M) ? gARow : 0;

    const unsigned sbase = (unsigned)__cvta_generic_to_shared(smem_raw);
    const float* apRow = A + (size_t)safeAR * Cn + aCbase;
    const float* bpRow = B + (size_t)bKrow * HC + head * Cn;

    // prologue: chunk 0 -> stage 0
    {
        unsigned aB = sbase;
        unsigned bB = sbase + 2 * AS_BYTES;
        #pragma unroll
        for (int j = 0; j < 4; j++)
            cp16(aB + (aRow * APAD + aCbase + 4 * j) * 4, apRow + 4 * j);
        #pragma unroll
        for (int j = 0; j < 4; j++) {
            int col = (bF4 + 8 * j) * 4;
            cp16(bB + (bKrow * BPAD + col) * 4, bpRow + col);
        }
        asm volatile("cp.async.commit_group;");
    }

    // fused init (head==0 blocks): out = features + bias, zero g_denom.
    // Runs while chunk-0 cp.async is in flight; exact fp32 (residual path).
    if (head == 0) {
        const float4* fp = (const float4*)(A + (size_t)rowBlk * Cn);
        const float4* bp = (const float4*)bias;
        float4*       op = (float4*)(out + (size_t)rowBlk * Cn);
        #pragma unroll
        for (int i = 0; i < 16; i++) {
            int idx = i * 256 + tid;        // 0..4095 float4s
            int row = idx >> 5;
            if (rowBlk + row < M) {
                float4 v = fp[idx];
                float4 b = bp[idx & 31];
                v.x += b.x; v.y += b.y; v.z += b.z; v.w += b.w;
                op[idx] = v;
            }
        }
        if (tid < TBM) {
            int gRow = rowBlk + tid;
            if (gRow < M) {
                #pragma unroll
                for (int h = 0; h < Hh; h++) g_denom[gRow * Hh + h] = 0.0f;
            }
        }
    }

    #pragma unroll
    for (int c = 0; c < 4; c++) {
        if (c < 3) {
            int st = (c + 1) & 1;
            int kc = (c + 1) * TBK;
            unsigned aB = sbase + st * AS_BYTES;
            unsigned bB = sbase + 2 * AS_BYTES + st * BS_BYTES;
            #pragma unroll
            for (int j = 0; j < 4; j++)
                cp16(aB + (aRow * APAD + aCbase + 4 * j) * 4, apRow + kc + 4 * j);
            #pragma unroll
            for (int j = 0; j < 4; j++) {
                int col = (bF4 + 8 * j) * 4;
                cp16(bB + (bKrow * BPAD + col) * 4, bpRow + (size_t)kc * HC + col);
            }
            asm volatile("cp.async.commit_group;");
            asm volatile("cp.async.wait_group 1;");
        } else {
            asm volatile("cp.async.wait_group 0;");
        }
        __syncthreads();

        const float* Asp = (const float*)(smem_raw + (c & 1) * AS_BYTES);
        const float* Bsp = (const float*)(smem_raw + 2 * AS_BYTES + (c & 1) * BS_BYTES);

        #pragma unroll
        for (int kk = 0; kk < 4; kk++) {
            const int kb = kk * 8;
            unsigned a[4][4], b[4][2];
            #pragma unroll
            for (int m = 0; m < 4; m++) {
                int r0 = warpM * 64 + m * 16 + gid;
                a[m][0] = __float_as_uint(Asp[r0 * APAD + kb + tig]);
                a[m][1] = __float_as_uint(Asp[(r0 + 8) * APAD + kb + tig]);
                a[m][2] = __float_as_uint(Asp[r0 * APAD + kb + tig + 4]);
                a[m][3] = __float_as_uint(Asp[(r0 + 8) * APAD + kb + tig + 4]);
            }
            #pragma unroll
            for (int n = 0; n < 4; n++) {
                int cb = warpN * 32 + n * 8 + gid;
                b[n][0] = __float_as_uint(Bsp[(kb + tig) * BPAD + cb]);
                b[n][1] = __float_as_uint(Bsp[(kb + tig + 4) * BPAD + cb]);
            }
            #pragma unroll
            for (int m = 0; m < 4; m++)
                #pragma unroll
                for (int n = 0; n < 4; n++)
                    mma_tf32(acc[m][n], a[m], b[n]);
        }
        __syncthreads();
    }

    // epilogue: stage fp16 tile into Cs
    #pragma unroll
    for (int m = 0; m < 4; m++) {
        int r0 = warpM * 64 + m * 16 + gid;
        #pragma unroll
        for (int n = 0; n < 4; n++) {
            int ch = warpN * 16 + n * 4 + tig;
            __half2 h01 = __floats2half2_rn(acc[m][n][0], acc[m][n][1]);
            __half2 h23 = __floats2half2_rn(acc[m][n][2], acc[m][n][3]);
            Cs[r0 * CH2S + ch]       = *(unsigned*)&h01;
            Cs[(r0 + 8) * CH2S + ch] = *(unsigned*)&h23;
        }
    }
    __syncthreads();

    // fused attention logits per row
    if (tid < TBM) {
        int gRow = rowBlk + tid;
        if (gRow < M) {
            const float* asv = att_src + head * Cn;
            const float* adv = att_dst + head * Cn;
            float ps = 0.f, pd = 0.f;
            #pragma unroll 8
            for (int i = 0; i < 64; i++) {
                unsigned u = Cs[tid * CH2S + i];
                float2 f = __half22float2(*(__half2*)&u);
                ps = fmaf(f.x, __ldg(asv + 2 * i), ps);
                ps = fmaf(f.y, __ldg(asv + 2 * i + 1), ps);
                pd = fmaf(f.x, __ldg(adv + 2 * i), pd);
                pd = fmaf(f.y, __ldg(adv + 2 * i + 1), pd);
            }
            g_asrc[gRow * Hh + head] = ps;
            g_adst[gRow * Hh + head] = pd;
        }
    }

    // coalesced fp16 store to g_h
    unsigned* gh = (unsigned*)g_h;
    #pragma unroll
    for (int i = 0; i < 32; i++) {
        int idx  = i * 256 + tid;
        int row  = idx >> 6;
        int ch   = idx & 63;
        int gRow = rowBlk + row;
        if (gRow < M)
            gh[(size_t)gRow * (HC / 2) + head * 64 + ch] = Cs[row * CH2S + ch];
    }
}

// ---------------- kernel 2: softmax denominators (no max pass) ---------------
__global__ void denom_kernel(const int* __restrict__ ei, int E, int Etot) {
    int e = blockIdx.x * blockDim.x + threadIdx.x;
    if (e >= Etot) return;
    int src, dst;
    if (e < E) { src = ei[e]; dst = ei[E + e]; }
    else       { src = e - E; dst = src; }
    #pragma unroll
    for (int h = 0; h < Hh; h++) {
        float v = g_asrc[src * Hh + h] + g_adst[dst * Hh + h];
        v = v > 0.f ? v : NEG_SLOPE * v;
        atomicAdd(&g_denom[dst * Hh + h], __expf(v));
    }
}

// ---------------- helper: accumulate 4 fp16 channels of one head -------------
__device__ __forceinline__ void acc_head(float4& acc4, uint2 u, float wgt) {
    float2 lo = __half22float2(*(const __half2*)&u.x);
    float2 hi = __half22float2(*(const __half2*)&u.y);
    acc4.x = fmaf(wgt, lo.x, acc4.x);
    acc4.y = fmaf(wgt, lo.y, acc4.y);
    acc4.z = fmaf(wgt, hi.x, acc4.z);
    acc4.w = fmaf(wgt, hi.y, acc4.w);
}

// ---------------- kernel 3: weighted scatter, warp per edge, fp16 h ----------
__global__ __launch_bounds__(256)
void scatter_kernel(const int* __restrict__ ei,
                    float* __restrict__ out, int E, int Etot) {
    int e = blockIdx.x * (blockDim.x >> 5) + (threadIdx.x >> 5);
    if (e >= Etot) return;
    int lane = threadIdx.x & 31;

    int src, dst;
    if (e < E) { src = ei[e]; dst = ei[E + e]; }
    else       { src = e - E; dst = src; }

    float wv = 0.f;
    if (lane < Hh) {
        float v = g_asrc[src * Hh + lane] + g_adst[dst * Hh + lane];
        v = v > 0.f ? v : NEG_SLOPE * v;
        wv = __expf(v) / (g_denom[dst * Hh + lane] + EPSV) * (1.0f / Hh);
    }
    float w0 = __shfl_sync(0xffffffffu, wv, 0);
    float w1 = __shfl_sync(0xffffffffu, wv, 1);
    float w2 = __shfl_sync(0xffffffffu, wv, 2);
    float w3 = __shfl_sync(0xffffffffu, wv, 3);
    float w4 = __shfl_sync(0xffffffffu, wv, 4);

    const uint2* hp = (const uint2*)(g_h + (size_t)src * HC) + lane;
    uint2 u0 = hp[0 * 32];
    uint2 u1 = hp[1 * 32];
    uint2 u2 = hp[2 * 32];
    uint2 u3 = hp[3 * 32];
    uint2 u4 = hp[4 * 32];

    float4 a = make_float4(0.f, 0.f, 0.f, 0.f);
    acc_head(a, u0, w0);
    acc_head(a, u1, w1);
    acc_head(a, u2, w2);
    acc_head(a, u3, w3);
    acc_head(a, u4, w4);

    float* op = out + (size_t)dst * Cn + lane * 4;
    asm volatile("red.global.add.v4.f32 [%0], {%1, %2, %3, %4};"
                 :: "l"(op), "f"(a.x), "f"(a.y), "f"(a.z), "f"(a.w)
                 : "memory");
}

// ---------------- launch -------------------------------------------------------
extern "C" void kernel_launch(void* const* d_in, const int* in_sizes, int n_in,
                              void* d_out, int out_size) {
    const float* features = (const float*)d_in[0];
    const float* W        = (const float*)d_in[1];
    const float* att_src  = (const float*)d_in[2];
    const float* att_dst  = (const float*)d_in[3];
    const float* bias     = (const float*)d_in[4];
    const int*   ei       = (const int*)d_in[5];
    float*       out      = (float*)d_out;

    const int Nn   = in_sizes[0] / Cn;   // 20000
    const int E    = in_sizes[5] / 2;    // 320000
    const int Etot = E + Nn;             // 340000

    // 1) GEMM (tf32 TC, pipelined) + fused logits + fused out-init/denom-zero
    {
        cudaFuncSetAttribute(gemm_tc_kernel,
                             cudaFuncAttributeMaxDynamicSharedMemorySize, SMEM_DYN);
        dim3 grid(Hh, (Nn + TBM - 1) / TBM);   // (5, 157)
        gemm_tc_kernel<<<grid, 256, SMEM_DYN>>>(features, W, att_src, att_dst,
                                                bias, out, Nn);
    }

    // 2) softmax denominators
    denom_kernel<<<(Etot + 255) / 256, 256>>>(ei, E, Etot);

    // 3) weighted scatter (8 edges per 256-thread block)
    scatter_kernel<<<(Etot + 7) / 8, 256>>>(ei, out, E, Etot);
}